// round 12
// baseline (speedup 1.0000x reference)
#include <cuda_runtime.h>
#include <math.h>

#define N_ELEMS 16384
#define NBINS   4096
#define NCTA    64
#define TPB     256
#define BPT     (NBINS / TPB)          // 16 bins per thread
#define CAP     64                     // per-bin capacity (expected <= ~8)
#define DELTA_F 0.1f
#define EPS_F   1e-12f
#define FIX_SCALE 4294967296.0         // 2^32

// Dynamic smem: [0, 16400) s_pref ints, [16640, 16640+65536) s_sorted
#define SMEM_SORT_OFF    16640          // 128B-aligned
#define SMEM_TOTAL_BYTES (SMEM_SORT_OFF + N_ELEMS * 4)

// ---- scratch (__device__ globals; zero-initialized at load) ----------------
__device__ float d_binned[NBINS * CAP];       // bin-major element storage (1 MB)
__device__ int   d_hist[NBINS];               // invariant: zero at launch entry
__device__ unsigned long long d_accum;        // invariant: zero at launch entry
__device__ int   d_done;                      // invariant: zero at launch entry
__device__ volatile int d_sense;
__device__ int   d_barcnt;

__device__ __forceinline__ int warp_iscan(int v) {
#pragma unroll
    for (int o = 1; o < 32; o <<= 1) {
        int n = __shfl_up_sync(0xffffffffu, v, o);
        if ((threadIdx.x & 31) >= o) v += n;
    }
    return v;
}

__global__ __launch_bounds__(TPB)
void ghm_fused(const float* __restrict__ logits,
               const float* __restrict__ targets,
               float* __restrict__ out) {
    extern __shared__ char smem[];
    int*   s_pref   = (int*)smem;                       // NBINS+1 entries
    float* s_sorted = (float*)(smem + SMEM_SORT_OFF);   // N_ELEMS entries
    __shared__ int s_wsum[8];
    __shared__ unsigned long long s_acc[8];
    __shared__ int s_last;

    const int t   = threadIdx.x;
    const int bid = blockIdx.x;
    const int i   = bid * TPB + t;     // this thread owns element i throughout

    int ls = d_sense;

    // ---- P0: prep g + histogram atomic (old value == within-bin rank) +
    //          direct scatter into fixed-capacity binned storage ----
    float x  = logits[i];
    float tv = targets[i];
    float pred = 1.0f / (1.0f + __expf(-x));
    float g    = fabsf(pred - tv);
    int   myb  = min((int)(g * (float)NBINS), NBINS - 1);
    int   rank = atomicAdd(&d_hist[myb], 1);
    if (rank < CAP) d_binned[myb * CAP + rank] = g;   // guard ~never fires

    // ---- B1 arrive (split: loss computed in barrier shadow) ----
    __syncthreads();
    int arr = -1;
    if (t == 0) { __threadfence(); arr = atomicAdd(&d_barcnt, 1); }

    float loss = fmaxf(x, 0.0f) - x * tv + log1pf(__expf(-fabsf(x)));

    // ---- B1 wait ----
    if (t == 0) {
        if (arr == NCTA - 1) { d_barcnt = 0; __threadfence(); d_sense = 1 - ls; }
        else { while (d_sense == ls) { } __threadfence(); }
    }
    __syncthreads();

    // ---- P1: full exclusive prefix of d_hist into this CTA's smem ----
    int h[BPT];
    int mybase;                        // exclusive prefix at this thread's first bin
    {
        const int4* hv = (const int4*)&d_hist[t * BPT];
        int4 a = hv[0], b = hv[1], c = hv[2], d = hv[3];
        h[0]=a.x; h[1]=a.y; h[2]=a.z; h[3]=a.w;
        h[4]=b.x; h[5]=b.y; h[6]=b.z; h[7]=b.w;
        h[8]=c.x; h[9]=c.y; h[10]=c.z; h[11]=c.w;
        h[12]=d.x; h[13]=d.y; h[14]=d.z; h[15]=d.w;
        int tot = 0;
#pragma unroll
        for (int k = 0; k < BPT; k++) tot += h[k];
        int incl = warp_iscan(tot);
        if ((t & 31) == 31) s_wsum[t >> 5] = incl;
        __syncthreads();
        if (t < 8) {
            int w = s_wsum[t];
#pragma unroll
            for (int o = 1; o < 8; o <<= 1) {
                int n = __shfl_up_sync(0xffu, w, o);
                if (t >= o) w += n;
            }
            s_wsum[t] = w;
        }
        __syncthreads();
        int base = incl - tot + ((t >> 5) ? s_wsum[(t >> 5) - 1] : 0);
        mybase = base;
#pragma unroll
        for (int k = 0; k < BPT; k++) {
            s_pref[t * BPT + k] = base;
            base += h[k];
        }
        if (t == TPB - 1) s_pref[NBINS] = N_ELEMS;
    }

    // ---- P2: compact d_binned -> contiguous s_sorted.
    // Fixed-shape: per bin load 2 float4 UNCONDITIONALLY (all 32 loads per
    // thread independent -> single latency exposure); conditionally store the
    // cb valid lanes to smem (stores are fire-and-forget). cb>8 spill is rare.
    {
        int base = mybase;
#pragma unroll
        for (int kb = 0; kb < BPT; kb++) {
            const float4* bp = (const float4*)&d_binned[(t * BPT + kb) * CAP];
            float4 v0 = bp[0];
            float4 v1 = bp[1];
            int cb = h[kb];
            if (0 < cb) s_sorted[base + 0] = v0.x;
            if (1 < cb) s_sorted[base + 1] = v0.y;
            if (2 < cb) s_sorted[base + 2] = v0.z;
            if (3 < cb) s_sorted[base + 3] = v0.w;
            if (4 < cb) s_sorted[base + 4] = v1.x;
            if (5 < cb) s_sorted[base + 5] = v1.y;
            if (6 < cb) s_sorted[base + 6] = v1.z;
            if (7 < cb) s_sorted[base + 7] = v1.w;
            if (cb > 8) {              // rare spill path
                const float* fp = &d_binned[(t * BPT + kb) * CAP];
                for (int k = 8; k < cb; k++) s_sorted[base + k] = fp[k];
            }
            base += cb;
        }
    }
    __syncthreads();

    // ---- P3: range-count query (interior via prefix diff, edges exact) ----
    // Interior bins [loBin+3, hiBin-3] guaranteed all-pass (>=1 bin-width
    // margin vs fp32 compare fuzz); bins outside [loBin-2, hiBin+2] guaranteed
    // all-fail; edge windows checked with the reference's exact fp32 compare.
    unsigned long long fixterm;
    {
        float p = g * (float)NBINS;
        int loBin = (int)floorf(p - 0.1f * (float)NBINS);
        int hiBin = (int)floorf(p + 0.1f * (float)NBINS);

        int iLo = min(max(loBin + 3, 0), NBINS);
        int iHi = min(max(hiBin - 2, 0), NBINS);
        int cnt = (iHi > iLo) ? (s_pref[iHi] - s_pref[iLo]) : 0;

        // lower edge window: bins [loBin-2, loBin+2] -> contiguous run in s_sorted
        {
            int a0 = max(loBin - 2, 0), b0 = min(loBin + 2, NBINS - 1);
            if (b0 >= a0) {
                int s = s_pref[a0], e = s_pref[b0 + 1];
#pragma unroll 8
                for (int idx = s; idx < e; idx++)
                    cnt += (fabsf(s_sorted[idx] - g) <= DELTA_F) ? 1 : 0;
            }
        }
        // upper edge window: bins [hiBin-2, hiBin+2]
        {
            int a1 = max(hiBin - 2, 0), b1 = min(hiBin + 2, NBINS - 1);
            if (b1 >= a1) {
                int s = s_pref[a1], e = s_pref[b1 + 1];
#pragma unroll 8
                for (int idx = s; idx < e; idx++)
                    cnt += (fabsf(s_sorted[idx] - g) <= DELTA_F) ? 1 : 0;
            }
        }

        float GD   = (float)cnt / DELTA_F;
        float beta = (float)N_ELEMS / (GD + EPS_F);
        float term = beta * loss;      // >= 0
        fixterm = (unsigned long long)((double)term * FIX_SCALE);
    }

    // ---- P4: deterministic finalize (u64 fixed-point; shuffle reduce) ----
    {
        unsigned long long v = fixterm;
#pragma unroll
        for (int off = 16; off > 0; off >>= 1)
            v += __shfl_down_sync(0xffffffffu, v, off);
        if ((t & 31) == 0) s_acc[t >> 5] = v;
        __syncthreads();
        if (t == 0) {
            unsigned long long w = 0;
#pragma unroll
            for (int k = 0; k < TPB / 32; k++) w += s_acc[k];
            atomicAdd(&d_accum, w);
            __threadfence();
            int ticket = atomicAdd(&d_done, 1);
            if (ticket == NCTA - 1) {
                __threadfence();
                unsigned long long total = atomicAdd(&d_accum, 0ULL);
                out[0] = (float)(((double)total / FIX_SCALE) / (double)N_ELEMS);
                d_accum = 0ULL;        // restore invariants for next replay
                d_done  = 0;
                s_last  = 1;
                __threadfence();
            } else {
                s_last = 0;
            }
        }
        __syncthreads();
        // Last CTA restores the hist zero-invariant. Safe: every CTA read
        // d_hist in P1 before incrementing d_done.
        if (s_last) {
            int4 z = make_int4(0, 0, 0, 0);
#pragma unroll
            for (int k = 0; k < NBINS / 4 / TPB; k++)   // 4 x STG.128 per thread
                ((int4*)d_hist)[k * TPB + t] = z;
        }
    }
}

// ---------------------------------------------------------------------------
extern "C" void kernel_launch(void* const* d_in, const int* in_sizes, int n_in,
                              void* d_out, int out_size) {
    const float* logits  = (const float*)d_in[0];
    const float* targets = (const float*)d_in[1];
    float* out = (float*)d_out;

    cudaFuncSetAttribute(ghm_fused, cudaFuncAttributeMaxDynamicSharedMemorySize,
                         SMEM_TOTAL_BYTES);
    ghm_fused<<<NCTA, TPB, SMEM_TOTAL_BYTES>>>(logits, targets, out);
}

// round 13
// speedup vs baseline: 1.6989x; 1.6989x over previous
#include <cuda_runtime.h>
#include <math.h>

#define N_ELEMS 16384
#define NBINS   4096
#define NCTA    128
#define TPB     128
#define BPT     (NBINS / TPB)          // 32 bins per thread
#define DELTA_F 0.1f
#define EPS_F   1e-12f
#define FIX_SCALE 4294967296.0         // 2^32

// Dynamic smem: [0, 16400) s_pref ints, [16640, 16640+65536) s_sorted
#define SMEM_SORT_OFF    16640          // 128B-aligned
#define SMEM_TOTAL_BYTES (SMEM_SORT_OFF + N_ELEMS * 4)

// ---- scratch (__device__ globals; zero-initialized at load) ----------------
__device__ float d_sorted[N_ELEMS];           // contiguous bin-sorted values
__device__ int   d_hist[NBINS];               // invariant: zero at launch entry
__device__ unsigned long long d_accum;        // invariant: zero at launch entry
__device__ int   d_done;                      // invariant: zero at launch entry
__device__ volatile int d_sense;
__device__ int   d_barcnt;

__device__ __forceinline__ int warp_iscan(int v) {
#pragma unroll
    for (int o = 1; o < 32; o <<= 1) {
        int n = __shfl_up_sync(0xffffffffu, v, o);
        if ((threadIdx.x & 31) >= o) v += n;
    }
    return v;
}

__global__ __launch_bounds__(TPB)
void ghm_fused(const float* __restrict__ logits,
               const float* __restrict__ targets,
               float* __restrict__ out) {
    extern __shared__ char smem[];
    int*   s_pref   = (int*)smem;                       // NBINS+1 entries
    float* s_sorted = (float*)(smem + SMEM_SORT_OFF);   // N_ELEMS entries
    __shared__ int s_wsum[4];
    __shared__ unsigned long long s_acc[4];
    __shared__ int s_last;

    const int t   = threadIdx.x;
    const int bid = blockIdx.x;
    const int i   = bid * TPB + t;     // this thread owns element i throughout

    int ls = d_sense;

    // ---- P0: prep g + histogram atomic; returned old value == within-bin
    //          rank (unique, 0..cb-1) -> reused later as scatter offset ----
    float x  = logits[i];
    float tv = targets[i];
    float pred = 1.0f / (1.0f + __expf(-x));
    float g    = fabsf(pred - tv);
    int   myb  = min((int)(g * (float)NBINS), NBINS - 1);
    int   rank = atomicAdd(&d_hist[myb], 1);

    // ---- B1 arrive (split: loss computed in barrier shadow) ----
    __syncthreads();
    int arr = -1;
    if (t == 0) { __threadfence(); arr = atomicAdd(&d_barcnt, 1); }

    float loss = fmaxf(x, 0.0f) - x * tv + log1pf(__expf(-fabsf(x)));

    // ---- B1 wait ----
    if (t == 0) {
        if (arr == NCTA - 1) { d_barcnt = 0; __threadfence(); d_sense = 1 - ls; }
        else { while (d_sense == ls) { } __threadfence(); }
    }
    ls = 1 - ls;
    __syncthreads();

    // ---- P1: full exclusive prefix of d_hist into this CTA's smem ----
    {
        int h[BPT];
        const int4* hv = (const int4*)&d_hist[t * BPT];
#pragma unroll
        for (int q = 0; q < BPT / 4; q++) {             // 8 x LDG.128
            int4 a = hv[q];
            h[q * 4 + 0] = a.x; h[q * 4 + 1] = a.y;
            h[q * 4 + 2] = a.z; h[q * 4 + 3] = a.w;
        }
        int tot = 0;
#pragma unroll
        for (int k = 0; k < BPT; k++) tot += h[k];
        int incl = warp_iscan(tot);
        if ((t & 31) == 31) s_wsum[t >> 5] = incl;
        __syncthreads();
        if (t < 4) {
            int w = s_wsum[t];
#pragma unroll
            for (int o = 1; o < 4; o <<= 1) {
                int n = __shfl_up_sync(0xfu, w, o);
                if (t >= o) w += n;
            }
            s_wsum[t] = w;
        }
        __syncthreads();
        int base = incl - tot + ((t >> 5) ? s_wsum[(t >> 5) - 1] : 0);
#pragma unroll
        for (int k = 0; k < BPT; k++) {
            s_pref[t * BPT + k] = base;
            base += h[k];
        }
        if (t == TPB - 1) s_pref[NBINS] = N_ELEMS;
    }
    __syncthreads();

    // ---- P2: scatter to contiguous d_sorted (single STG; rank from P0) ----
    d_sorted[s_pref[myb] + rank] = g;

    // ---- B2 arrive ----
    __syncthreads();
    if (t == 0) { __threadfence(); arr = atomicAdd(&d_barcnt, 1); }

    // B2 shadow: interior count + edge ranges (depend only on s_pref and g).
    // Interior bins [loBin+3, hiBin-3] guaranteed all-pass (>=1 bin-width
    // margin vs fp32 compare fuzz); bins outside [loBin-2, hiBin+2] guaranteed
    // all-fail; edge windows checked below with the exact fp32 compare.
    int cnt, e0s, e0e, e1s, e1e;
    {
        float p = g * (float)NBINS;
        int loBin = (int)floorf(p - 0.1f * (float)NBINS);
        int hiBin = (int)floorf(p + 0.1f * (float)NBINS);

        int iLo = min(max(loBin + 3, 0), NBINS);
        int iHi = min(max(hiBin - 2, 0), NBINS);
        cnt = (iHi > iLo) ? (s_pref[iHi] - s_pref[iLo]) : 0;

        int a0 = max(loBin - 2, 0), b0 = min(loBin + 2, NBINS - 1);
        e0s = s_pref[a0]; e0e = (b0 >= a0) ? s_pref[b0 + 1] : e0s;
        int a1 = max(hiBin - 2, 0), b1 = min(hiBin + 2, NBINS - 1);
        e1s = s_pref[a1]; e1e = (b1 >= a1) ? s_pref[b1 + 1] : e1s;
    }

    // ---- B2 wait ----
    if (t == 0) {
        if (arr == NCTA - 1) { d_barcnt = 0; __threadfence(); d_sense = 1 - ls; }
        else { while (d_sense == ls) { } __threadfence(); }
    }
    __syncthreads();

    // ---- stage full sorted array into this CTA's smem (coalesced) ----
    {
        const float4* src = (const float4*)d_sorted;
        float4*       dst = (float4*)s_sorted;
#pragma unroll
        for (int k = 0; k < N_ELEMS / 4 / TPB; k++)     // 32 x LDG.128
            dst[k * TPB + t] = src[k * TPB + t];
    }
    __syncthreads();

    // ---- P3: exact edge-window checks from smem ----
    unsigned long long fixterm;
    {
#pragma unroll 8
        for (int idx = e0s; idx < e0e; idx++)
            cnt += (fabsf(s_sorted[idx] - g) <= DELTA_F) ? 1 : 0;
#pragma unroll 8
        for (int idx = e1s; idx < e1e; idx++)
            cnt += (fabsf(s_sorted[idx] - g) <= DELTA_F) ? 1 : 0;

        float GD   = (float)cnt / DELTA_F;
        float beta = (float)N_ELEMS / (GD + EPS_F);
        float term = beta * loss;      // >= 0
        fixterm = (unsigned long long)((double)term * FIX_SCALE);
    }

    // ---- P4: deterministic finalize (u64 fixed-point; shuffle reduce) ----
    {
        unsigned long long v = fixterm;
#pragma unroll
        for (int off = 16; off > 0; off >>= 1)
            v += __shfl_down_sync(0xffffffffu, v, off);
        if ((t & 31) == 0) s_acc[t >> 5] = v;
        __syncthreads();
        if (t == 0) {
            unsigned long long w = s_acc[0] + s_acc[1] + s_acc[2] + s_acc[3];
            atomicAdd(&d_accum, w);
            __threadfence();
            int ticket = atomicAdd(&d_done, 1);
            if (ticket == NCTA - 1) {
                __threadfence();
                unsigned long long total = atomicAdd(&d_accum, 0ULL);
                out[0] = (float)(((double)total / FIX_SCALE) / (double)N_ELEMS);
                d_accum = 0ULL;        // restore invariants for next replay
                d_done  = 0;
                s_last  = 1;
                __threadfence();
            } else {
                s_last = 0;
            }
        }
        __syncthreads();
        // Last CTA restores the hist zero-invariant. Safe: every CTA read
        // d_hist in P1 (pre-B2) and incremented d_done only afterwards.
        if (s_last) {
            int4 z = make_int4(0, 0, 0, 0);
#pragma unroll
            for (int k = 0; k < NBINS / 4 / TPB; k++)   // 8 x STG.128 per thread
                ((int4*)d_hist)[k * TPB + t] = z;
        }
    }
}

// ---------------------------------------------------------------------------
extern "C" void kernel_launch(void* const* d_in, const int* in_sizes, int n_in,
                              void* d_out, int out_size) {
    const float* logits  = (const float*)d_in[0];
    const float* targets = (const float*)d_in[1];
    float* out = (float*)d_out;

    cudaFuncSetAttribute(ghm_fused, cudaFuncAttributeMaxDynamicSharedMemorySize,
                         SMEM_TOTAL_BYTES);
    ghm_fused<<<NCTA, TPB, SMEM_TOTAL_BYTES>>>(logits, targets, out);
}